// round 8
// baseline (speedup 1.0000x reference)
#include <cuda_runtime.h>
#include <cuda_fp16.h>
#include <cstdint>

// ---------------- problem constants ----------------
#define NB 64          // batch
#define NSQ 16         // steps
#define NO 31          // real opcodes
#define NOP 32         // padded opcode slots
#define ND 1024        // hidden dim
#define ND4 256        // float4 slices per row
#define NOG 8          // opcodes per GEMM CTA
#define NGRP 4         // opcode groups

// ---------------- GEMM tiling ----------------
#define GN 32                  // N per CTA
#define GK 64                  // halfs per stage along contraction
#define STAGES 4
#define NIT (ND / GK)          // 16 k-stages
#define GEMM_THREADS 256
#define NCTA 128               // 32 n-tiles x 4 groups; single wave (<=148 SMs)

#define BBYTES (NOG * GN * 128)  // 32 KB
#define ABYTES (64 * 128)        // 8 KB
#define STAGE_BYTES (BBYTES + ABYTES)
#define SMEM_TOTAL (STAGES * STAGE_BYTES + 1024)   // 164864 B -> 1 CTA/SM

#define SWZ(x) ((x) ^ (((x) >> 3) & 0x70))

// ---------------- device scratch (static; allocation is forbidden) ------------
__device__ __align__(256) __half g_Kt[(size_t)NOP * ND * ND];  // [o][n][d] fp16 (slot 31 zero)
__device__ __align__(256) __half g_H[NB * ND];                 // fp16 h (A operand)
__device__ __align__(256) float  g_w[NSQ * NB * NOP];          // softmax weights, all steps
__device__ __align__(256) float  g_gate[NSQ * NB];             // sigmoid(gate logit), all steps
__device__ __align__(256) float  g_P[(size_t)NGRP * NB * ND];  // group partials, 1 MB

// grid barrier state (zero-init; count returns to 0 after every release)
__device__ unsigned g_bar_count;
__device__ unsigned g_bar_release;

// ---------------- PTX helpers (<= sm_90 features; safe for compute_103) -------
__device__ __forceinline__ uint32_t smem_u32(const void* p) {
    uint32_t a;
    asm("{ .reg .u64 t; cvta.to.shared.u64 t, %1; cvt.u32.u64 %0, t; }" : "=r"(a) : "l"(p));
    return a;
}
__device__ __forceinline__ void cp16(uint32_t dst, const void* src) {
    asm volatile("cp.async.cg.shared.global [%0], [%1], 16;\n"
                 :: "r"(dst), "l"((unsigned long long)__cvta_generic_to_global(src)) : "memory");
}
#define CP_COMMIT() asm volatile("cp.async.commit_group;" ::: "memory")
#define CP_WAIT2()  asm volatile("cp.async.wait_group %0;" :: "n"(STAGES - 2) : "memory")
#define CP_WAIT0()  asm volatile("cp.async.wait_group 0;" ::: "memory")

__device__ __forceinline__ void ldm_x4(uint32_t& r0, uint32_t& r1, uint32_t& r2,
                                       uint32_t& r3, uint32_t addr) {
    asm volatile("ldmatrix.sync.aligned.m8n8.x4.shared.b16 {%0,%1,%2,%3}, [%4];"
                 : "=r"(r0), "=r"(r1), "=r"(r2), "=r"(r3) : "r"(addr));
}
__device__ __forceinline__ void ldm_x2(uint32_t& r0, uint32_t& r1, uint32_t addr) {
    asm volatile("ldmatrix.sync.aligned.m8n8.x2.shared.b16 {%0,%1}, [%2];"
                 : "=r"(r0), "=r"(r1) : "r"(addr));
}
__device__ __forceinline__ void mma16816(float* c, uint32_t a0, uint32_t a1,
                                         uint32_t a2, uint32_t a3,
                                         uint32_t b0, uint32_t b1) {
    asm volatile(
        "mma.sync.aligned.m16n8k16.row.col.f32.f16.f16.f32 "
        "{%0,%1,%2,%3}, {%4,%5,%6,%7}, {%8,%9}, {%0,%1,%2,%3};"
        : "+f"(c[0]), "+f"(c[1]), "+f"(c[2]), "+f"(c[3])
        : "r"(a0), "r"(a1), "r"(a2), "r"(a3), "r"(b0), "r"(b1));
}

// Monotonic-release grid barrier. All NCTA CTAs co-resident (single wave).
// base = g_bar_release sampled at kernel entry (before any arrival can release).
__device__ __forceinline__ void grid_sync(unsigned base, unsigned gen) {
    __syncthreads();
    __threadfence();
    if (threadIdx.x == 0) {
        if (atomicAdd(&g_bar_count, 1u) == NCTA - 1u) {
            atomicExch(&g_bar_count, 0u);
            __threadfence();
            atomicAdd(&g_bar_release, 1u);
        } else {
            while (*(volatile unsigned*)&g_bar_release - base < gen) {}
        }
    }
    __syncthreads();
}

// ============================================================================
// Kernel 1: transpose + convert  K[o][d][n] fp32  ->  g_Kt[o][n][d] fp16
// grid (32, 32, 32), block (32, 8).  Slot o==31: zeros (pad opcode).
// ============================================================================
__global__ void ktrans_kernel(const float* __restrict__ K) {
    __shared__ float tile[32][33];
    const int o = blockIdx.z;
    const int n0 = blockIdx.x * 32;
    const int d0 = blockIdx.y * 32;
    const int tx = threadIdx.x, ty = threadIdx.y;

    __half* dst = g_Kt + ((size_t)o << 20);
    if (o == NO) {
#pragma unroll
        for (int i = 0; i < 4; i++)
            dst[(size_t)(n0 + ty + i * 8) * ND + d0 + tx] = __float2half(0.0f);
        return;
    }
    const float* src = K + ((size_t)o << 20);
#pragma unroll
    for (int i = 0; i < 4; i++) {
        int dl = ty + i * 8;
        tile[dl][tx] = src[(size_t)(d0 + dl) * ND + n0 + tx];
    }
    __syncthreads();
#pragma unroll
    for (int i = 0; i < 4; i++) {
        int nl = ty + i * 8;
        dst[(size_t)(n0 + nl) * ND + d0 + tx] = __float2half(tile[tx][nl]);
    }
}

// ============================================================================
// Kernel 2: precompute softmax weights + gates for ALL steps (h-independent).
// grid (64), 32 threads.
// ============================================================================
__global__ void prep_kernel(const float* __restrict__ logits,
                            const float* __restrict__ operands) {
    const int b = blockIdx.x;
    const int tid = threadIdx.x;
#pragma unroll 1
    for (int s = 0; s < NSQ; s++) {
        float l = (tid < NO) ? logits[(b * NSQ + s) * NO + tid] : -1e30f;
        float m = l;
#pragma unroll
        for (int off = 16; off; off >>= 1)
            m = fmaxf(m, __shfl_xor_sync(0xffffffff, m, off));
        float e = (tid < NO) ? expf(l - m) : 0.0f;
        float sm = e;
#pragma unroll
        for (int off = 16; off; off >>= 1)
            sm += __shfl_xor_sync(0xffffffff, sm, off);
        g_w[(s * NB + b) * NOP + tid] = e / sm;   // slot 31 -> 0
        if (tid == 0)
            g_gate[s * NB + b] =
                1.0f / (1.0f + expf(-operands[(b * NSQ + s) * 4 + 3]));
    }
}

// ============================================================================
// Kernel 3: persistent fused scan.  grid 128, 256 threads, ~161 KB smem.
// Per step: 8-op packed GEMM -> group partials -> grid sync -> inline gated
// update (h in registers of 16384 owner threads) -> grid sync.
// ============================================================================
__global__ void __launch_bounds__(GEMM_THREADS, 1)
persist_kernel(const float* __restrict__ signal, float* __restrict__ out) {
    extern __shared__ char smem_raw[];
    const uint32_t sb = (smem_u32(smem_raw) + 1023u) & ~1023u;
    const int tid  = threadIdx.x;
    const int lane = tid & 31;
    const int wid  = tid >> 5;
    const int wm   = wid & 1;    // M 32-half
    const int wn   = wid >> 1;   // N 8-col slice
    const int og   = blockIdx.x >> 5;          // opcode group 0..3
    const int n0   = (blockIdx.x & 31) * GN;   // n-tile 0..992

    const unsigned bar_base = *(volatile unsigned*)&g_bar_release;
    unsigned gen = 0;

    // ---- h slice ownership: thread (cta, tid<128) owns float4 (ob, od4) ----
    const int slice = blockIdx.x * 128 + tid;  // 0..16383
    const int ob  = slice >> 8;
    const int od4 = slice & 255;
    float4 hv = make_float4(0.f, 0.f, 0.f, 0.f);
    if (tid < 128) {
        hv = reinterpret_cast<const float4*>(signal)[ob * ND4 + od4];
        __half2 h01 = __floats2half2_rn(hv.x, hv.y);
        __half2 h23 = __floats2half2_rn(hv.z, hv.w);
        uint2 hh;
        hh.x = *reinterpret_cast<uint32_t*>(&h01);
        hh.y = *reinterpret_cast<uint32_t*>(&h23);
        reinterpret_cast<uint2*>(g_H)[ob * ND4 + od4] = hh;
    }
    grid_sync(bar_base, ++gen);

    const __half* Ksrc = g_Kt + ((size_t)(og * NOG) << 20);

    auto issue_loads = [&](int j) {
        const uint32_t base  = sb + (j & (STAGES - 1)) * STAGE_BYTES;
        const uint32_t abase = base + BBYTES;
        const int kk = j * GK;
#pragma unroll
        for (int i = 0; i < 8; i++) {   // B: 8 ops x 32 rows x 8 x16B
            int idx = tid + i * GEMM_THREADS;
            int op = idx >> 8, row = (idx >> 3) & 31, c = idx & 7;
            cp16(base + op * 4096 + SWZ(row * 128 + c * 16),
                 (const char*)(Ksrc + ((size_t)op << 20) +
                               (size_t)(n0 + row) * ND + kk) + c * 16);
        }
#pragma unroll
        for (int i = 0; i < 2; i++) {   // A: 64 rows x 8 x16B
            int idx = tid + i * GEMM_THREADS;
            int row = idx >> 3, c = idx & 7;
            cp16(abase + SWZ(row * 128 + c * 16),
                 (const char*)(g_H + (size_t)row * ND + kk) + c * 16);
        }
    };

    const int a_row = (lane & 15);
    const int a_kb  = (lane >> 4) * 16;
    const int b_row = (lane & 7);
    const int b_kb  = ((lane >> 3) & 1) * 16;

#pragma unroll 1
    for (int t = 0; t < NSQ; t++) {
        float acc[NOG][2][4];
#pragma unroll
        for (int op = 0; op < NOG; op++)
#pragma unroll
            for (int mi = 0; mi < 2; mi++)
#pragma unroll
                for (int c = 0; c < 4; c++) acc[op][mi][c] = 0.0f;

        for (int j = 0; j < STAGES - 1; j++) { issue_loads(j); CP_COMMIT(); }

#pragma unroll 1
        for (int j = 0; j < NIT; j++) {
            CP_WAIT2();
            __syncthreads();
            if (j + STAGES - 1 < NIT) issue_loads(j + STAGES - 1);
            CP_COMMIT();

            const uint32_t base  = sb + (j & (STAGES - 1)) * STAGE_BYTES;
            const uint32_t abase = base + BBYTES;
#pragma unroll
            for (int kc = 0; kc < 4; kc++) {
                uint32_t a[2][4];
#pragma unroll
                for (int mi = 0; mi < 2; mi++) {
                    int row = wm * 32 + mi * 16 + a_row;
                    ldm_x4(a[mi][0], a[mi][1], a[mi][2], a[mi][3],
                           abase + SWZ(row * 128 + kc * 32 + a_kb));
                }
#pragma unroll
                for (int op = 0; op < NOG; op++) {
                    uint32_t b0, b1;
                    ldm_x2(b0, b1,
                           base + op * 4096 +
                           SWZ((wn * 8 + b_row) * 128 + kc * 32 + b_kb));
                    mma16816(acc[op][0], a[0][0], a[0][1], a[0][2], a[0][3], b0, b1);
                    mma16816(acc[op][1], a[1][0], a[1][1], a[1][2], a[1][3], b0, b1);
                }
            }
            __syncthreads();
        }
        CP_WAIT0();   // drain before smem slots are refilled next step

        // ---- epilogue: fold step-t softmax weights, write group partials ----
        const int r_base = wm * 32 + (lane >> 2);
        const int cb0    = wn * 8 + (lane & 3) * 2;
        const float* wt = g_w + (size_t)t * NB * NOP;
#pragma unroll
        for (int mi = 0; mi < 2; mi++) {
            const int rA = r_base + mi * 16;
            const int rB = rA + 8;
            float2 sA = make_float2(0.f, 0.f);
            float2 sB = make_float2(0.f, 0.f);
#pragma unroll
            for (int op = 0; op < NOG; op++) {
                const float wA = wt[rA * NOP + og * NOG + op];
                const float wB = wt[rB * NOP + og * NOG + op];
                sA.x += wA * acc[op][mi][0];
                sA.y += wA * acc[op][mi][1];
                sB.x += wB * acc[op][mi][2];
                sB.y += wB * acc[op][mi][3];
            }
            *reinterpret_cast<float2*>(g_P + ((size_t)og * NB + rA) * ND + n0 + cb0) = sA;
            *reinterpret_cast<float2*>(g_P + ((size_t)og * NB + rB) * ND + n0 + cb0) = sB;
        }

        grid_sync(bar_base, ++gen);   // partials visible everywhere

        // ---- inline gated update on owner threads ----
        if (tid < 128) {
            const float4* P4 = reinterpret_cast<const float4*>(g_P);
            float4 acc4 = make_float4(0.f, 0.f, 0.f, 0.f);
#pragma unroll
            for (int g = 0; g < NGRP; g++) {
                float4 p = __ldcg(P4 + ((size_t)g * NB + ob) * ND4 + od4);
                acc4.x += p.x; acc4.y += p.y; acc4.z += p.z; acc4.w += p.w;
            }
            const float s  = g_gate[t * NB + ob];
            const float is = 1.0f - s;
            hv.x = s * acc4.x + is * hv.x;
            hv.y = s * acc4.y + is * hv.y;
            hv.z = s * acc4.z + is * hv.z;
            hv.w = s * acc4.w + is * hv.w;
            if (t + 1 < NSQ) {
                __half2 h01 = __floats2half2_rn(hv.x, hv.y);
                __half2 h23 = __floats2half2_rn(hv.z, hv.w);
                uint2 hh;
                hh.x = *reinterpret_cast<uint32_t*>(&h01);
                hh.y = *reinterpret_cast<uint32_t*>(&h23);
                reinterpret_cast<uint2*>(g_H)[ob * ND4 + od4] = hh;
            } else {
                reinterpret_cast<float4*>(out)[ob * ND4 + od4] = hv;
            }
        }
        if (t + 1 < NSQ) grid_sync(bar_base, ++gen);  // g_H visible for next A
    }
}

// ============================================================================
// Launch
// ============================================================================
extern "C" void kernel_launch(void* const* d_in, const int* in_sizes, int n_in,
                              void* d_out, int out_size) {
    const float* logits   = (const float*)d_in[0];  // (64,16,31)
    const float* operands = (const float*)d_in[1];  // (64,16,4)
    const float* signal   = (const float*)d_in[2];  // (64,1024)
    const float* kernels  = (const float*)d_in[3];  // (31,1024,1024)
    float* out = (float*)d_out;                     // (64,1024)

    static bool attr_set = false;
    if (!attr_set) {
        cudaFuncSetAttribute(persist_kernel,
                             cudaFuncAttributeMaxDynamicSharedMemorySize, SMEM_TOTAL);
        attr_set = true;
    }

    ktrans_kernel<<<dim3(32, 32, NOP), dim3(32, 8)>>>(kernels);
    prep_kernel<<<NB, 32>>>(logits, operands);
    persist_kernel<<<NCTA, GEMM_THREADS, SMEM_TOTAL>>>(signal, out);
}